// round 5
// baseline (speedup 1.0000x reference)
#include <cuda_runtime.h>
#include <cuda_bf16.h>
#include <stdint.h>
#include <math.h>

// ---------------- problem constants ----------------
#define NNODES 50000
#define NKEEP  320000
#define D_IN   128
#define D_OUT  256
#define D_HID  512
#define BN_EPS 1e-5f

typedef __nv_bfloat16 bf16;
typedef __nv_bfloat162 bf162;

// ---------------- device scratch ----------------
__device__ float g_agg [(size_t)NNODES * D_OUT];
__device__ bf16  g_T   [(size_t)NNODES * D_HID];
__device__ bf16  g_V   [(size_t)NNODES * D_OUT];
__device__ float g_REX1[(size_t)NNODES * D_IN];
__device__ float g_REX2[(size_t)NNODES * D_IN];
__device__ bf16  g_wb[655360];
__device__ int   g_src1[NKEEP], g_dst1[NKEEP], g_src2[NKEEP], g_dst2[NKEEP];
__device__ unsigned char g_mA[NNODES], g_mB[NNODES];
__device__ float g_stats[2 * D_HID];       // zero-init; scaleshift re-zeroes after read
__device__ float g_sc1[D_HID], g_sh1[D_HID];
__device__ float g_sc2[D_HID], g_sh2[D_HID];
__device__ float g_acc[8];                 // 0:loss1 1:loss2 2:cl 3:cnt1 4:cnt2 (zeroed in detect_k)
__device__ int   g_flags[2];

// ---------------- detection (also zeroes accumulators each replay) ----------------
__global__ void detect_k(const int* __restrict__ e1w, const unsigned char* __restrict__ m1b) {
    if (threadIdx.x == 0 && blockIdx.x == 0) {
        int nz = 0;
        for (int i = 0; i < 64; ++i) nz += (e1w[2 * i + 1] != 0);
        g_flags[0] = (nz == 0) ? 1 : 0;
        int nzb = 0;
        for (int i = 0; i < 256; ++i) if (i & 3) nzb += (m1b[i] != 0);
        g_flags[1] = (nzb == 0) ? 1 : 0;
        for (int i = 0; i < 8; ++i) g_acc[i] = 0.f;
    }
}

// fused edge conversion + mask conversion + mask count
__global__ void prep_k(const int* __restrict__ eraw, int* __restrict__ src, int* __restrict__ dst,
                       const void* __restrict__ mraw, unsigned char* __restrict__ m,
                       float* __restrict__ cnt) {
    int e = blockIdx.x * 256 + threadIdx.x;
    if (e < NKEEP) {
        if (g_flags[0]) { src[e] = eraw[2 * e]; dst[e] = eraw[2 * (NKEEP + e)]; }
        else            { src[e] = eraw[e];     dst[e] = eraw[NKEEP + e]; }
    }
    if ((int)blockIdx.x * 256 < NNODES) {
        unsigned char v = 0;
        if (e < NNODES) {
            if (g_flags[1]) v = (((const unsigned int*)mraw)[e] != 0u);
            else            v = (((const unsigned char*)mraw)[e] != 0);
            m[e] = v;
        }
        __shared__ int s[256];
        s[threadIdx.x] = v;
        __syncthreads();
        for (int o = 128; o; o >>= 1) {
            if (threadIdx.x < o) s[threadIdx.x] += s[threadIdx.x + o];
            __syncthreads();
        }
        if (threadIdx.x == 0) atomicAdd(cnt, (float)s[0]);
    }
}

// ---------------- weight fp32 -> bf16 ----------------
__global__ void convw_k(const float* __restrict__ src, bf16* __restrict__ dst, int n) {
    int i = blockIdx.x * 256 + threadIdx.x;
    if (i < n) dst[i] = __float2bfloat16_rn(src[i]);
}

// ---------------- elementwise ----------------
// agg = where(mask,0,x)
__global__ void maskagg_k(const float* __restrict__ X, float* __restrict__ AGG,
                          const unsigned char* __restrict__ m) {
    size_t i = (size_t)blockIdx.x * blockDim.x + threadIdx.x;
    if (i >= (size_t)NNODES * D_IN) return;
    int row = (int)(i >> 7);
    AGG[i] = m[row] ? 0.f : X[i];
}

// OUT(fp32) = relu(bf16V*sc+sh), optional row mask
__global__ void postbn_k(const bf16* __restrict__ V, float* __restrict__ OUT,
                         const float* __restrict__ sc, const float* __restrict__ sh,
                         const unsigned char* __restrict__ m, int C, int cshift) {
    size_t i = (size_t)blockIdx.x * blockDim.x + threadIdx.x;
    if (i >= (size_t)NNODES * C) return;
    int c = (int)(i & (size_t)(C - 1));
    float v = fmaxf(__bfloat162float(V[i]) * sc[c] + sh[c], 0.f);
    if (m) {
        int row = (int)(i >> cshift);
        if (m[row]) v = 0.f;
    }
    OUT[i] = v;
}

// ---------------- scatter-add variants ----------------
// fp32 input, masked (layer 0): AGG[dst] += mask?0:X[src]
__global__ void scatterf_k(const float* __restrict__ X, float* __restrict__ AGG,
                           const int* __restrict__ src, const int* __restrict__ dst,
                           const unsigned char* __restrict__ m) {
    int e = blockIdx.x * blockDim.y + threadIdx.y;
    if (e >= NKEEP) return;
    int s = src[e];
    if (m[s]) return;
    int d = dst[e];
    int c = threadIdx.x;                       // 0..31, d4 = 32
    float4 v = ((const float4*)X)[(size_t)s * 32 + c];
    float* p = AGG + ((size_t)d * 32 + c) * 4;
    asm volatile("red.global.add.v4.f32 [%0], {%1,%2,%3,%4};"
                 :: "l"(p), "f"(v.x), "f"(v.y), "f"(v.z), "f"(v.w) : "memory");
}

// bf16 input with BN+relu gather (layers 1/2); MASK: skip if mask[src]. C=256, 8 elems/thread.
template <bool MASK>
__global__ void scatterb_k(const bf16* __restrict__ X, float* __restrict__ AGG,
                           const int* __restrict__ src, const int* __restrict__ dst,
                           const float* __restrict__ sc, const float* __restrict__ sh,
                           const unsigned char* __restrict__ m) {
    int e = blockIdx.x * blockDim.y + threadIdx.y;
    if (e >= NKEEP) return;
    int s = src[e];
    if (MASK && m[s]) return;
    int d = dst[e];
    int c = threadIdx.x;                       // 0..31, 8 bf16 each
    uint4 raw = ((const uint4*)X)[(size_t)s * 32 + c];
    const bf162* h = (const bf162*)&raw;
    int k0 = c * 8;
    float o[8];
#pragma unroll
    for (int j = 0; j < 4; ++j) {
        float2 f = __bfloat1622float2(h[j]);
        o[2 * j]     = fmaxf(f.x * sc[k0 + 2 * j]     + sh[k0 + 2 * j],     0.f);
        o[2 * j + 1] = fmaxf(f.y * sc[k0 + 2 * j + 1] + sh[k0 + 2 * j + 1], 0.f);
    }
    float* p = AGG + (size_t)d * 256 + k0;
    asm volatile("red.global.add.v4.f32 [%0], {%1,%2,%3,%4};"
                 :: "l"(p), "f"(o[0]), "f"(o[1]), "f"(o[2]), "f"(o[3]) : "memory");
    asm volatile("red.global.add.v4.f32 [%0], {%1,%2,%3,%4};"
                 :: "l"(p + 4), "f"(o[4]), "f"(o[5]), "f"(o[6]), "f"(o[7]) : "memory");
}

// ---------------- BN scale/shift (reads stats, re-zeroes) ----------------
__global__ void scaleshift_k(float* __restrict__ sum, float* __restrict__ sq,
                             const float* __restrict__ g, const float* __restrict__ b,
                             float* __restrict__ sc, float* __restrict__ sh, int C) {
    int c = blockIdx.x * blockDim.x + threadIdx.x;
    if (c >= C) return;
    const float invN = 1.f / (float)NNODES;
    float s_ = sum[c], q_ = sq[c];
    sum[c] = 0.f; sq[c] = 0.f;
    float mu  = s_ * invN;
    float var = q_ * invN - mu * mu;
    float rs  = rsqrtf(var + BN_EPS);
    float s   = g[c] * rs;
    sc[c] = s;
    sh[c] = b[c] - mu * s;
}

// ---------------- bf16 tensor-core GEMM, bf16 output, fused stats epilogue ------
// AT = float (raw agg, no BN) or bf16 (T, with BN+relu at A-load).
// Block 128x128, BK=32, 8 warps (2x4); m16n8k16 bf16 mma; double-buffered smem.
template <typename AT, bool TA>
__global__ void __launch_bounds__(256, 2)
bgemm_k(const AT* __restrict__ A, const bf16* __restrict__ W, bf16* __restrict__ C,
        int M, int K, int Ncol, const float* __restrict__ sc, const float* __restrict__ sh,
        float* __restrict__ ssum, float* __restrict__ ssq) {
    constexpr bool A16 = (sizeof(AT) == 2);
    __shared__ __align__(16) bf16 As[2][128][40];
    __shared__ __align__(16) bf16 Bs[2][32][136];
    __shared__ float s_sum[128], s_sq[128];
    const int tid  = threadIdx.x;
    const int wid  = tid >> 5, lane = tid & 31;
    const int warpM = wid & 1, warpN = wid >> 1;
    const int by = blockIdx.y * 128, bx = blockIdx.x * 128;
    const int lq = lane >> 2, lr = lane & 3;
    // fp32 A-load layout
    const int arF = tid >> 3, acF = (tid & 7) * 4;
    // bf16 A-load layout
    const int arH = tid >> 2, acH = (tid & 3) * 8;
    // B-load layout
    const int bkr = tid >> 4, bc = (tid & 15) * 8;
    // ldmatrix addressing
    const int aRow = (lane & 7) + ((lane >> 3) & 1) * 8;
    const int aKh  = (lane >> 4) * 8;
    const int bRow = lane & 15;
    const int bColH = (lane >> 4) * 8;

    const uint32_t bsBase = (uint32_t)__cvta_generic_to_shared(&Bs[0][0][0]);
    const uint32_t asBase = (uint32_t)__cvta_generic_to_shared(&As[0][0][0]);

    float acc[4][4][4] = {};
    float4 aRegF[4];
    uint4  aRegH[2];
    uint4  bReg[2];
    const int nT = K >> 5;

    // ---- helpers as macros to keep one code path ----
#define LOADA(kb)                                                                   \
    if (!A16) {                                                                     \
        _Pragma("unroll")                                                           \
        for (int it = 0; it < 4; ++it) {                                            \
            int grow = by + arF + it * 32;                                          \
            aRegF[it] = make_float4(0.f, 0.f, 0.f, 0.f);                            \
            if (grow < M) aRegF[it] = *(const float4*)((const float*)A + (size_t)grow * K + (kb) + acF); \
        }                                                                           \
    } else {                                                                        \
        _Pragma("unroll")                                                           \
        for (int it = 0; it < 2; ++it) {                                            \
            int grow = by + arH + it * 64;                                          \
            aRegH[it] = make_uint4(0u, 0u, 0u, 0u);                                 \
            if (grow < M) aRegH[it] = *(const uint4*)((const bf16*)A + (size_t)grow * K + (kb) + acH); \
        }                                                                           \
    }

#define STOREA(buf, kb)                                                             \
    if (!A16) {                                                                     \
        _Pragma("unroll")                                                           \
        for (int it = 0; it < 4; ++it) {                                            \
            float4 v = aRegF[it];                                                   \
            *(bf162*)&As[buf][arF + it * 32][acF]     = __floats2bfloat162_rn(v.x, v.y); \
            *(bf162*)&As[buf][arF + it * 32][acF + 2] = __floats2bfloat162_rn(v.z, v.w); \
        }                                                                           \
    } else {                                                                        \
        _Pragma("unroll")                                                           \
        for (int it = 0; it < 2; ++it) {                                            \
            const bf162* hh = (const bf162*)&aRegH[it];                             \
            int k0 = (kb) + acH;                                                    \
            bool dead = TA && (by + arH + it * 64 >= M);                            \
            _Pragma("unroll")                                                       \
            for (int j = 0; j < 4; ++j) {                                           \
                float2 f = __bfloat1622float2(hh[j]);                               \
                if (TA) {                                                           \
                    f.x = fmaxf(f.x * sc[k0 + 2 * j]     + sh[k0 + 2 * j],     0.f);\
                    f.y = fmaxf(f.y * sc[k0 + 2 * j + 1] + sh[k0 + 2 * j + 1], 0.f);\
                    if (dead) { f.x = 0.f; f.y = 0.f; }                             \
                }                                                                   \
                *(bf162*)&As[buf][arH + it * 64][acH + 2 * j] = __floats2bfloat162_rn(f.x, f.y); \
            }                                                                       \
        }                                                                           \
    }

    // ---- tile 0 ----
    LOADA(0)
#pragma unroll
    for (int it = 0; it < 2; ++it)
        bReg[it] = *(const uint4*)(W + (size_t)(bkr + it * 16) * Ncol + bx + bc);
    STOREA(0, 0)
#pragma unroll
    for (int it = 0; it < 2; ++it)
        *(uint4*)&Bs[0][bkr + it * 16][bc] = bReg[it];
    __syncthreads();

    for (int t = 0; t < nT; ++t) {
        const int buf = t & 1;
        if (t + 1 < nT) {
            const int kb = (t + 1) * 32;
            LOADA(kb)
#pragma unroll
            for (int it = 0; it < 2; ++it)
                bReg[it] = *(const uint4*)(W + (size_t)(kb + bkr + it * 16) * Ncol + bx + bc);
        }

#pragma unroll
        for (int k16 = 0; k16 < 2; ++k16) {
            const int kk = k16 * 16;
            uint32_t af[4][4], bf[4][2];
#pragma unroll
            for (int mt = 0; mt < 4; ++mt) {
                int rm = warpM * 64 + mt * 16;
                uint32_t addr = asBase + (uint32_t)(((buf * 128 + rm + aRow) * 40 + kk + aKh) * 2);
                asm volatile("ldmatrix.sync.aligned.m8n8.x4.shared.b16 {%0,%1,%2,%3}, [%4];"
                             : "=r"(af[mt][0]), "=r"(af[mt][1]), "=r"(af[mt][2]), "=r"(af[mt][3])
                             : "r"(addr));
            }
#pragma unroll
            for (int p = 0; p < 2; ++p) {
                int cn = warpN * 32 + p * 16 + bColH;
                uint32_t addr = bsBase + (uint32_t)(((buf * 32 + kk + bRow) * 136 + cn) * 2);
                asm volatile("ldmatrix.sync.aligned.m8n8.x4.trans.shared.b16 {%0,%1,%2,%3}, [%4];"
                             : "=r"(bf[2 * p][0]), "=r"(bf[2 * p][1]),
                               "=r"(bf[2 * p + 1][0]), "=r"(bf[2 * p + 1][1])
                             : "r"(addr));
            }
#pragma unroll
            for (int mt = 0; mt < 4; ++mt)
#pragma unroll
                for (int nt = 0; nt < 4; ++nt) {
                    asm volatile(
                        "mma.sync.aligned.m16n8k16.row.col.f32.bf16.bf16.f32 "
                        "{%0,%1,%2,%3}, {%4,%5,%6,%7}, {%8,%9}, {%0,%1,%2,%3};"
                        : "+f"(acc[mt][nt][0]), "+f"(acc[mt][nt][1]),
                          "+f"(acc[mt][nt][2]), "+f"(acc[mt][nt][3])
                        : "r"(af[mt][0]), "r"(af[mt][1]), "r"(af[mt][2]), "r"(af[mt][3]),
                          "r"(bf[nt][0]), "r"(bf[nt][1]));
                }
        }

        if (t + 1 < nT) {
            const int nb = buf ^ 1;
            const int kb = (t + 1) * 32;
            STOREA(nb, kb)
#pragma unroll
            for (int it = 0; it < 2; ++it)
                *(uint4*)&Bs[nb][bkr + it * 16][bc] = bReg[it];
            __syncthreads();
        }
    }

    // ---- store C (bf16) ----
#pragma unroll
    for (int mt = 0; mt < 4; ++mt) {
        int r0 = by + warpM * 64 + mt * 16 + lq;
        int r1 = r0 + 8;
#pragma unroll
        for (int nt = 0; nt < 4; ++nt) {
            int c0 = bx + warpN * 32 + nt * 8 + lr * 2;
            if (r0 < M) *(bf162*)(C + (size_t)r0 * Ncol + c0) = __floats2bfloat162_rn(acc[mt][nt][0], acc[mt][nt][1]);
            if (r1 < M) *(bf162*)(C + (size_t)r1 * Ncol + c0) = __floats2bfloat162_rn(acc[mt][nt][2], acc[mt][nt][3]);
        }
    }

    // ---- fused BN stats epilogue ----
    for (int i = tid; i < 128; i += 256) { s_sum[i] = 0.f; s_sq[i] = 0.f; }
    __syncthreads();
#pragma unroll
    for (int nt = 0; nt < 4; ++nt) {
        float s0 = 0.f, q0 = 0.f, s1 = 0.f, q1 = 0.f;
#pragma unroll
        for (int mt = 0; mt < 4; ++mt) {
            float a0 = acc[mt][nt][0], a1 = acc[mt][nt][1];
            float a2 = acc[mt][nt][2], a3 = acc[mt][nt][3];
            s0 += a0 + a2; q0 += a0 * a0 + a2 * a2;
            s1 += a1 + a3; q1 += a1 * a1 + a3 * a3;
        }
#pragma unroll
        for (int o = 4; o < 32; o <<= 1) {
            s0 += __shfl_xor_sync(0xffffffffu, s0, o);
            q0 += __shfl_xor_sync(0xffffffffu, q0, o);
            s1 += __shfl_xor_sync(0xffffffffu, s1, o);
            q1 += __shfl_xor_sync(0xffffffffu, q1, o);
        }
        if (lq == 0) {
            int c0 = warpN * 32 + nt * 8 + lr * 2;
            atomicAdd(&s_sum[c0],     s0); atomicAdd(&s_sq[c0],     q0);
            atomicAdd(&s_sum[c0 + 1], s1); atomicAdd(&s_sq[c0 + 1], q1);
        }
    }
    __syncthreads();
    for (int i = tid; i < 128; i += 256) {
        atomicAdd(&ssum[bx + i], s_sum[i]);
        atomicAdd(&ssq[bx + i],  s_sq[i]);
    }
#undef LOADA
#undef STOREA
}

// ---------------- losses ----------------
__global__ void passloss_k(const float* __restrict__ REX, const float* __restrict__ X,
                           const unsigned char* __restrict__ m, float* __restrict__ acc) {
    int warp = threadIdx.x >> 5, lane = threadIdx.x & 31;
    int row = blockIdx.x * 8 + warp;
    float contrib = 0.f;
    if (row < NNODES) {
        float4 a = ((const float4*)(REX + (size_t)row * D_IN))[lane];
        float4 b = ((const float4*)(X   + (size_t)row * D_IN))[lane];
        float dot = a.x * b.x + a.y * b.y + a.z * b.z + a.w * b.w;
        float na  = a.x * a.x + a.y * a.y + a.z * a.z + a.w * a.w;
        float nb  = b.x * b.x + b.y * b.y + b.z * b.z + b.w * b.w;
#pragma unroll
        for (int o = 16; o; o >>= 1) {
            dot += __shfl_down_sync(0xffffffffu, dot, o);
            na  += __shfl_down_sync(0xffffffffu, na , o);
            nb  += __shfl_down_sync(0xffffffffu, nb , o);
        }
        if (lane == 0 && m[row]) {
            float c = dot / (fmaxf(sqrtf(na), 1e-12f) * fmaxf(sqrtf(nb), 1e-12f));
            contrib = 1.f - c;
        }
    }
    __shared__ float s[8];
    if (lane == 0) s[warp] = contrib;
    __syncthreads();
    if (threadIdx.x == 0) {
        float t = 0.f;
#pragma unroll
        for (int j = 0; j < 8; ++j) t += s[j];
        atomicAdd(acc, t);
    }
}

__global__ void cl_k(const float* __restrict__ A, const float* __restrict__ B, float* __restrict__ acc) {
    int warp = threadIdx.x >> 5, lane = threadIdx.x & 31;
    int row = blockIdx.x * 8 + warp;
    float contrib = 0.f;
    if (row < NNODES) {
        float4 a = ((const float4*)(A + (size_t)row * D_IN))[lane];
        float4 b = ((const float4*)(B + (size_t)row * D_IN))[lane];
        float dot = a.x * b.x + a.y * b.y + a.z * b.z + a.w * b.w;
        float na  = a.x * a.x + a.y * a.y + a.z * a.z + a.w * a.w;
        float nb  = b.x * b.x + b.y * b.y + b.z * b.z + b.w * b.w;
#pragma unroll
        for (int o = 16; o; o >>= 1) {
            dot += __shfl_down_sync(0xffffffffu, dot, o);
            na  += __shfl_down_sync(0xffffffffu, na , o);
            nb  += __shfl_down_sync(0xffffffffu, nb , o);
        }
        if (lane == 0) {
            float c = dot / (fmaxf(sqrtf(na), 1e-12f) * fmaxf(sqrtf(nb), 1e-12f));
            contrib = 1.f - c;
        }
    }
    __shared__ float s[8];
    if (lane == 0) s[warp] = contrib;
    __syncthreads();
    if (threadIdx.x == 0) {
        float t = 0.f;
#pragma unroll
        for (int j = 0; j < 8; ++j) t += s[j];
        atomicAdd(acc, t);
    }
}

__global__ void final_k(float* __restrict__ out) {
    out[0] = g_acc[0] / g_acc[3] + g_acc[1] / g_acc[4] + 0.1f * (g_acc[2] / (float)NNODES);
}

extern "C" void kernel_launch(void* const* d_in, const int* in_sizes, int n_in,
                              void* d_out, int out_size) {
    const float* x = (const float*)d_in[0];
    const int* e1raw = (const int*)d_in[1];
    const int* e2raw = (const int*)d_in[2];
    const unsigned char* m1raw = (const unsigned char*)d_in[3];
    const unsigned char* m2raw = (const unsigned char*)d_in[4];
    const float* e0_w1 = (const float*)d_in[6];
    const float* e0_w2 = (const float*)d_in[7];
    const float* e0_bg = (const float*)d_in[8];
    const float* e0_bb = (const float*)d_in[9];
    const float* e0_ng = (const float*)d_in[10];
    const float* e0_nb = (const float*)d_in[11];
    const float* e1_w1 = (const float*)d_in[12];
    const float* e1_w2 = (const float*)d_in[13];
    const float* e1_bg = (const float*)d_in[14];
    const float* e1_bb = (const float*)d_in[15];
    const float* e1_ng = (const float*)d_in[16];
    const float* e1_nb = (const float*)d_in[17];
    const float* dw1   = (const float*)d_in[18];
    const float* dw2   = (const float*)d_in[19];
    const float* dbg   = (const float*)d_in[20];
    const float* dbb   = (const float*)d_in[21];
    const float* dng   = (const float*)d_in[22];
    const float* dnb   = (const float*)d_in[23];
    float* out = (float*)d_out;

    float *p_agg, *p_REX1, *p_REX2, *p_stats, *p_sc1, *p_sh1, *p_sc2, *p_sh2, *p_acc;
    bf16 *p_T, *p_V, *p_wb;
    int *p_src1, *p_dst1, *p_src2, *p_dst2;
    unsigned char *p_mA, *p_mB;
    cudaGetSymbolAddress((void**)&p_agg,  g_agg);
    cudaGetSymbolAddress((void**)&p_T,    g_T);
    cudaGetSymbolAddress((void**)&p_V,    g_V);
    cudaGetSymbolAddress((void**)&p_REX1, g_REX1);
    cudaGetSymbolAddress((void**)&p_REX2, g_REX2);
    cudaGetSymbolAddress((void**)&p_stats,g_stats);
    cudaGetSymbolAddress((void**)&p_sc1,  g_sc1);
    cudaGetSymbolAddress((void**)&p_sh1,  g_sh1);
    cudaGetSymbolAddress((void**)&p_sc2,  g_sc2);
    cudaGetSymbolAddress((void**)&p_sh2,  g_sh2);
    cudaGetSymbolAddress((void**)&p_acc,  g_acc);
    cudaGetSymbolAddress((void**)&p_src1, g_src1);
    cudaGetSymbolAddress((void**)&p_dst1, g_dst1);
    cudaGetSymbolAddress((void**)&p_src2, g_src2);
    cudaGetSymbolAddress((void**)&p_dst2, g_dst2);
    cudaGetSymbolAddress((void**)&p_mA,   g_mA);
    cudaGetSymbolAddress((void**)&p_mB,   g_mB);
    cudaGetSymbolAddress((void**)&p_wb,   g_wb);

    float* p_sum = p_stats;
    float* p_sq  = p_stats + D_HID;

    bf16* wb_e0w1 = p_wb + 0;
    bf16* wb_e0w2 = p_wb + 65536;
    bf16* wb_e1w1 = p_wb + 196608;
    bf16* wb_e1w2 = p_wb + 327680;
    bf16* wb_dw1  = p_wb + 458752;
    bf16* wb_dw2  = p_wb + 589824;

    const int MB = (NNODES + 127) / 128;
    const unsigned EB = (NKEEP + 255) / 256;
    dim3 sblk(32, 8);
    const unsigned sg = (NKEEP + 7) / 8;

    // ---- setup, ordered so launch #5 is the first bgemm (ncu -s 5 -c 1) ----
    detect_k<<<1, 32>>>(e1raw, m1raw);                                   // 0 (zeroes g_acc)
    prep_k<<<EB, 256>>>(e1raw, p_src1, p_dst1, m1raw, p_mA, p_acc + 3);  // 1
    convw_k<<<(65536 + 255) / 256, 256>>>(e0_w1, wb_e0w1, 65536);        // 2
    maskagg_k<<<(unsigned)(((size_t)NNODES * D_IN + 255) / 256), 256>>>(x, p_agg, p_mA); // 3
    scatterf_k<<<sg, sblk>>>(x, p_agg, p_src1, p_dst1, p_mA);            // 4
    bgemm_k<float, false><<<dim3(D_HID / 128, MB), 256>>>(p_agg, wb_e0w1, p_T, NNODES, D_IN, D_HID, nullptr, nullptr, p_sum, p_sq); // 5 <- profiled
    // remaining setup
    prep_k<<<EB, 256>>>(e2raw, p_src2, p_dst2, m2raw, p_mB, p_acc + 4);
    convw_k<<<(131072 + 255) / 256, 256>>>(e0_w2, wb_e0w2, 131072);
    convw_k<<<(131072 + 255) / 256, 256>>>(e1_w1, wb_e1w1, 131072);
    convw_k<<<(131072 + 255) / 256, 256>>>(e1_w2, wb_e1w2, 131072);
    convw_k<<<(131072 + 255) / 256, 256>>>(dw1,   wb_dw1,  131072);
    convw_k<<<(65536  + 255) / 256, 256>>>(dw2,   wb_dw2,  65536);

    for (int pass = 0; pass < 2; ++pass) {
        const int* src = pass ? p_src2 : p_src1;
        const int* dst = pass ? p_dst2 : p_dst1;
        const unsigned char* m = pass ? p_mB : p_mA;
        float* REX = pass ? p_REX2 : p_REX1;

        if (pass == 1) {
            maskagg_k<<<(unsigned)(((size_t)NNODES * D_IN + 255) / 256), 256>>>(x, p_agg, m);
            scatterf_k<<<sg, sblk>>>(x, p_agg, src, dst, m);
            bgemm_k<float, false><<<dim3(D_HID / 128, MB), 256>>>(p_agg, wb_e0w1, p_T, NNODES, D_IN, D_HID, nullptr, nullptr, p_sum, p_sq);
        }
        // ---- encoder layer 0 (GEMM1 already issued above) ----
        scaleshift_k<<<2, 256>>>(p_sum, p_sq, e0_bg, e0_bb, p_sc1, p_sh1, D_HID);
        bgemm_k<bf16, true><<<dim3(D_OUT / 128, MB), 256>>>(p_T, wb_e0w2, p_V, NNODES, D_HID, D_OUT, p_sc1, p_sh1, p_sum, p_sq);
        scaleshift_k<<<1, 256>>>(p_sum, p_sq, e0_ng, e0_nb, p_sc2, p_sh2, D_OUT);
        postbn_k<<<(unsigned)(((size_t)NNODES * D_OUT + 255) / 256), 256>>>(p_V, p_agg, p_sc2, p_sh2, nullptr, D_OUT, 8);

        // ---- encoder layer 1 ----
        scatterb_k<false><<<sg, sblk>>>(p_V, p_agg, src, dst, p_sc2, p_sh2, nullptr);
        bgemm_k<float, false><<<dim3(D_HID / 128, MB), 256>>>(p_agg, wb_e1w1, p_T, NNODES, D_OUT, D_HID, nullptr, nullptr, p_sum, p_sq);
        scaleshift_k<<<2, 256>>>(p_sum, p_sq, e1_bg, e1_bb, p_sc1, p_sh1, D_HID);
        bgemm_k<bf16, true><<<dim3(D_OUT / 128, MB), 256>>>(p_T, wb_e1w2, p_V, NNODES, D_HID, D_OUT, p_sc1, p_sh1, p_sum, p_sq);
        scaleshift_k<<<1, 256>>>(p_sum, p_sq, e1_ng, e1_nb, p_sc2, p_sh2, D_OUT);
        // agg(decoder) = mask ? 0 : relu(bn(V1))
        postbn_k<<<(unsigned)(((size_t)NNODES * D_OUT + 255) / 256), 256>>>(p_V, p_agg, p_sc2, p_sh2, m, D_OUT, 8);

        // ---- decoder ----
        scatterb_k<true><<<sg, sblk>>>(p_V, p_agg, src, dst, p_sc2, p_sh2, m);
        bgemm_k<float, false><<<dim3(D_HID / 128, MB), 256>>>(p_agg, wb_dw1, p_T, NNODES, D_OUT, D_HID, nullptr, nullptr, p_sum, p_sq);
        scaleshift_k<<<2, 256>>>(p_sum, p_sq, dbg, dbb, p_sc1, p_sh1, D_HID);
        bgemm_k<bf16, true><<<dim3(D_IN / 128, MB), 256>>>(p_T, wb_dw2, p_V, NNODES, D_HID, D_IN, p_sc1, p_sh1, p_sum, p_sq);
        scaleshift_k<<<1, 128>>>(p_sum, p_sq, dng, dnb, p_sc2, p_sh2, D_IN);
        postbn_k<<<(unsigned)(((size_t)NNODES * D_IN + 255) / 256), 256>>>(p_V, REX, p_sc2, p_sh2, nullptr, D_IN, 7);

        passloss_k<<<(NNODES + 7) / 8, 256>>>(REX, x, m, p_acc + pass);
    }

    cl_k<<<(NNODES + 7) / 8, 256>>>(p_REX2, p_REX1, p_acc + 2);
    final_k<<<1, 1>>>(out);
    (void)in_sizes; (void)n_in; (void)out_size;
}

// round 7
// speedup vs baseline: 1.1084x; 1.1084x over previous
#include <cuda_runtime.h>
#include <cuda_bf16.h>
#include <stdint.h>
#include <math.h>

// ---------------- problem constants ----------------
#define NNODES 50000
#define NKEEP  320000
#define D_IN   128
#define D_OUT  256
#define D_HID  512
#define BN_EPS 1e-5f
#define YBLK   391                    // row blocks per pass
#define PADN   (YBLK * 128)           // 50048, padded rows per pass

typedef __nv_bfloat16 bf16;
typedef __nv_bfloat162 bf162;

// ---------------- device scratch (stacked: [2*PADN, C]) ----------------
__device__ float g_agg [(size_t)2 * PADN * D_OUT];
__device__ float g_T   [(size_t)2 * PADN * D_HID];
__device__ float g_V   [(size_t)2 * PADN * D_OUT];
__device__ float g_REX [(size_t)2 * PADN * D_IN];
__device__ bf16  g_wb[655360];
__device__ int   g_src1[NKEEP], g_dst1[NKEEP], g_src2[NKEEP], g_dst2[NKEEP];
__device__ unsigned char g_mA[NNODES], g_mB[NNODES];
__device__ float g_stats[2048];            // [half][ sum(512) | sq(512) ]
__device__ float g_sc1[2 * D_HID], g_sh1[2 * D_HID];
__device__ float g_sc2[2 * D_HID], g_sh2[2 * D_HID];
__device__ float g_acc[8];                 // 0:loss1 1:loss2 2:cl 3:cnt1 4:cnt2
__device__ int   g_flags[2];

// ---------------- detection (also zeroes accumulators each replay) ----------------
__global__ void detect_k(const int* __restrict__ e1w, const unsigned char* __restrict__ m1b) {
    if (threadIdx.x == 0 && blockIdx.x == 0) {
        int nz = 0;
        for (int i = 0; i < 64; ++i) nz += (e1w[2 * i + 1] != 0);
        g_flags[0] = (nz == 0) ? 1 : 0;
        int nzb = 0;
        for (int i = 0; i < 256; ++i) if (i & 3) nzb += (m1b[i] != 0);
        g_flags[1] = (nzb == 0) ? 1 : 0;
        for (int i = 0; i < 8; ++i) g_acc[i] = 0.f;
    }
}

// fused edge conversion + mask conversion + mask count
__global__ void prep_k(const int* __restrict__ eraw, int* __restrict__ src, int* __restrict__ dst,
                       const void* __restrict__ mraw, unsigned char* __restrict__ m,
                       float* __restrict__ cnt) {
    int e = blockIdx.x * 256 + threadIdx.x;
    if (e < NKEEP) {
        if (g_flags[0]) { src[e] = eraw[2 * e]; dst[e] = eraw[2 * (NKEEP + e)]; }
        else            { src[e] = eraw[e];     dst[e] = eraw[NKEEP + e]; }
    }
    if ((int)blockIdx.x * 256 < NNODES) {
        unsigned char v = 0;
        if (e < NNODES) {
            if (g_flags[1]) v = (((const unsigned int*)mraw)[e] != 0u);
            else            v = (((const unsigned char*)mraw)[e] != 0);
            m[e] = v;
        }
        __shared__ int s[256];
        s[threadIdx.x] = v;
        __syncthreads();
        for (int o = 128; o; o >>= 1) {
            if (threadIdx.x < o) s[threadIdx.x] += s[threadIdx.x + o];
            __syncthreads();
        }
        if (threadIdx.x == 0) atomicAdd(cnt, (float)s[0]);
    }
}

// ---------------- weight fp32 -> bf16 ----------------
__global__ void convw_k(const float* __restrict__ src, bf16* __restrict__ dst, int n) {
    int i = blockIdx.x * 256 + threadIdx.x;
    if (i < n) dst[i] = __float2bfloat16_rn(src[i]);
}

// ---------------- elementwise ----------------
// agg[both halves] = where(mask,0,x)   (layer-0 self term)
__global__ void maskagg_k(const float* __restrict__ X, float* __restrict__ AGG,
                          const unsigned char* __restrict__ mA, const unsigned char* __restrict__ mB) {
    size_t i = (size_t)blockIdx.x * blockDim.x + threadIdx.x;
    const size_t hsz = (size_t)NNODES * D_IN;
    if (i >= 2 * hsz) return;
    int pass = i >= hsz;
    size_t j = i - (pass ? hsz : 0);
    int row = (int)(j >> 7);
    const unsigned char* m = pass ? mB : mA;
    AGG[j + (size_t)pass * PADN * D_IN] = m[row] ? 0.f : X[j];
}

// OUT = relu(V*sc+sh) for both halves, optional per-pass row mask
template <bool MASK>
__global__ void postbn_k(const float* __restrict__ V, float* __restrict__ OUT,
                         const float* __restrict__ sc, const float* __restrict__ sh,
                         const unsigned char* __restrict__ mA, const unsigned char* __restrict__ mB) {
    size_t i = (size_t)blockIdx.x * blockDim.x + threadIdx.x;
    const size_t hsz = (size_t)NNODES * D_OUT;
    if (i >= 2 * hsz) return;
    int pass = i >= hsz;
    size_t j = i - (pass ? hsz : 0);
    int c = (int)(j & (D_OUT - 1));
    size_t vi = j + (size_t)pass * PADN * D_OUT;
    float v = fmaxf(V[vi] * sc[pass * 512 + c] + sh[pass * 512 + c], 0.f);
    if (MASK) {
        int row = (int)(j >> 8);
        const unsigned char* m = pass ? mB : mA;
        if (m[row]) v = 0.f;
    }
    OUT[vi] = v;
}

// ---------------- merged scatter-add (both passes, one launch) ----------------
// layer-0: fp32 x, masked source skip
__global__ void scatterf_k(const float* __restrict__ X, float* __restrict__ AGG,
                           const int* __restrict__ s1, const int* __restrict__ d1,
                           const int* __restrict__ s2, const int* __restrict__ d2,
                           const unsigned char* __restrict__ mA, const unsigned char* __restrict__ mB) {
    int slot = blockIdx.x * blockDim.y + threadIdx.y;
    if (slot >= 2 * NKEEP) return;
    int pass = slot >= NKEEP;
    int e = slot - (pass ? NKEEP : 0);
    int s = pass ? s2[e] : s1[e];
    if ((pass ? mB : mA)[s]) return;
    int d = pass ? d2[e] : d1[e];
    int c = threadIdx.x;                         // 0..31
    float4 v = ((const float4*)X)[(size_t)s * 32 + c];
    float* p = AGG + (((size_t)(pass ? PADN : 0) + d) * 32 + c) * 4;
    asm volatile("red.global.add.v4.f32 [%0], {%1,%2,%3,%4};"
                 :: "l"(p), "f"(v.x), "f"(v.y), "f"(v.z), "f"(v.w) : "memory");
}

// layers 1/2: fp32 V with BN+relu on gather; MASK: skip masked source
template <bool MASK>
__global__ void scatterb_k(const float* __restrict__ V, float* __restrict__ AGG,
                           const int* __restrict__ s1, const int* __restrict__ d1,
                           const int* __restrict__ s2, const int* __restrict__ d2,
                           const float* __restrict__ sc, const float* __restrict__ sh,
                           const unsigned char* __restrict__ mA, const unsigned char* __restrict__ mB) {
    int slot = blockIdx.x * blockDim.y + threadIdx.y;
    if (slot >= 2 * NKEEP) return;
    int pass = slot >= NKEEP;
    int e = slot - (pass ? NKEEP : 0);
    int s = pass ? s2[e] : s1[e];
    if (MASK && (pass ? mB : mA)[s]) return;
    int d = pass ? d2[e] : d1[e];
    int c = threadIdx.x;                         // 0..63
    size_t base = (size_t)(pass ? PADN : 0);
    float4 v = ((const float4*)V)[(base + s) * 64 + c];
    int k0 = pass * 512 + c * 4;
    v.x = fmaxf(v.x * sc[k0 + 0] + sh[k0 + 0], 0.f);
    v.y = fmaxf(v.y * sc[k0 + 1] + sh[k0 + 1], 0.f);
    v.z = fmaxf(v.z * sc[k0 + 2] + sh[k0 + 2], 0.f);
    v.w = fmaxf(v.w * sc[k0 + 3] + sh[k0 + 3], 0.f);
    float* p = AGG + ((base + d) * 64 + c) * 4;
    asm volatile("red.global.add.v4.f32 [%0], {%1,%2,%3,%4};"
                 :: "l"(p), "f"(v.x), "f"(v.y), "f"(v.z), "f"(v.w) : "memory");
}

// ---------------- BN scale/shift, both halves (reads stats, re-zeroes) --------
__global__ void scaleshift_k(float* __restrict__ stats,
                             const float* __restrict__ g, const float* __restrict__ b,
                             float* __restrict__ sc, float* __restrict__ sh, int C) {
    int idx = blockIdx.x * blockDim.x + threadIdx.x;
    if (idx >= 2 * C) return;
    int half = idx >= C;
    int c = idx - (half ? C : 0);
    float* st = stats + half * 1024;
    const float invN = 1.f / (float)NNODES;
    float s_ = st[c], q_ = st[512 + c];
    st[c] = 0.f; st[512 + c] = 0.f;
    float mu  = s_ * invN;
    float var = q_ * invN - mu * mu;
    float rs  = rsqrtf(var + BN_EPS);
    float s   = g[c] * rs;
    sc[half * 512 + c] = s;
    sh[half * 512 + c] = b[c] - mu * s;
}

// ---------------- bf16 tensor-core GEMM, stacked halves, fused stats ----------
// C[2*PADN,Ncol] = A'[2*PADN,K] @ W[K,Ncol]; TA: A'=relu(A*sc+sh) at smem store.
// blockIdx.y in [0,782): half = y>=391. Per-half BN params and stats.
template <bool TA>
__global__ void __launch_bounds__(256, 2)
bgemm_k(const float* __restrict__ A, const bf16* __restrict__ W, float* __restrict__ C,
        int K, int Ncol, const float* __restrict__ sc, const float* __restrict__ sh,
        float* __restrict__ stats) {
    __shared__ __align__(16) bf16 As[2][128][40];
    __shared__ __align__(16) bf16 Bs[2][32][136];
    __shared__ float s_sum[128], s_sq[128];
    const int tid  = threadIdx.x;
    const int wid  = tid >> 5, lane = tid & 31;
    const int warpM = wid & 1, warpN = wid >> 1;
    const int half = blockIdx.y >= YBLK;
    const int by = blockIdx.y * 128, bx = blockIdx.x * 128;
    const int lby = by - half * PADN;          // local row base within pass
    const float* scp = sc + half * 512;
    const float* shp = sh + half * 512;
    float* st = stats + half * 1024;
    const int lq = lane >> 2, lr = lane & 3;
    const int ar = tid >> 3, ac = (tid & 7) * 4;
    const int bkr = tid >> 4, bc = (tid & 15) * 8;
    const int brow = lane & 15;
    const int aRow = (lane & 7) + ((lane >> 3) & 1) * 8;
    const int aKh  = (lane >> 4) * 8;

    const uint32_t bsBase = (uint32_t)__cvta_generic_to_shared(&Bs[0][0][0]);
    const uint32_t asBase = (uint32_t)__cvta_generic_to_shared(&As[0][0][0]);

    float acc[4][4][4] = {};
    float4 aReg[4];
    uint4  bReg[2];
    const int nT = K >> 5;

    // ---- tile 0 ----
#pragma unroll
    for (int it = 0; it < 4; ++it) {
        aReg[it] = make_float4(0.f, 0.f, 0.f, 0.f);
        if (lby + ar + it * 32 < NNODES)
            aReg[it] = *(const float4*)(A + (size_t)(by + ar + it * 32) * K + ac);
    }
#pragma unroll
    for (int it = 0; it < 2; ++it)
        bReg[it] = *(const uint4*)(W + (size_t)(bkr + it * 16) * Ncol + bx + bc);
#pragma unroll
    for (int it = 0; it < 4; ++it) {
        float4 v = aReg[it];
        if (TA) {
            int k0 = ac;
            v.x = fmaxf(v.x * scp[k0 + 0] + shp[k0 + 0], 0.f);
            v.y = fmaxf(v.y * scp[k0 + 1] + shp[k0 + 1], 0.f);
            v.z = fmaxf(v.z * scp[k0 + 2] + shp[k0 + 2], 0.f);
            v.w = fmaxf(v.w * scp[k0 + 3] + shp[k0 + 3], 0.f);
            if (lby + ar + it * 32 >= NNODES) v = make_float4(0.f, 0.f, 0.f, 0.f);
        }
        *(bf162*)&As[0][ar + it * 32][ac]     = __floats2bfloat162_rn(v.x, v.y);
        *(bf162*)&As[0][ar + it * 32][ac + 2] = __floats2bfloat162_rn(v.z, v.w);
    }
#pragma unroll
    for (int it = 0; it < 2; ++it)
        *(uint4*)&Bs[0][bkr + it * 16][bc] = bReg[it];
    __syncthreads();

    for (int t = 0; t < nT; ++t) {
        const int buf = t & 1;
        if (t + 1 < nT) {
            const int kb = (t + 1) * 32;
#pragma unroll
            for (int it = 0; it < 4; ++it) {
                aReg[it] = make_float4(0.f, 0.f, 0.f, 0.f);
                if (lby + ar + it * 32 < NNODES)
                    aReg[it] = *(const float4*)(A + (size_t)(by + ar + it * 32) * K + kb + ac);
            }
#pragma unroll
            for (int it = 0; it < 2; ++it)
                bReg[it] = *(const uint4*)(W + (size_t)(kb + bkr + it * 16) * Ncol + bx + bc);
        }

#pragma unroll
        for (int k16 = 0; k16 < 2; ++k16) {
            const int kk = k16 * 16;
            uint32_t af[4][4], bf[4][2];
#pragma unroll
            for (int mt = 0; mt < 4; ++mt) {
                int rm = warpM * 64 + mt * 16;
                uint32_t addr = asBase + (uint32_t)(((buf * 128 + rm + aRow) * 40 + kk + aKh) * 2);
                asm volatile("ldmatrix.sync.aligned.m8n8.x4.shared.b16 {%0,%1,%2,%3}, [%4];"
                             : "=r"(af[mt][0]), "=r"(af[mt][1]), "=r"(af[mt][2]), "=r"(af[mt][3])
                             : "r"(addr));
            }
#pragma unroll
            for (int nt = 0; nt < 4; ++nt) {
                int cn = warpN * 32 + nt * 8;
                uint32_t addr = bsBase + (uint32_t)(((buf * 32 + kk + brow) * 136 + cn) * 2);
                asm volatile("ldmatrix.sync.aligned.m8n8.x2.trans.shared.b16 {%0,%1}, [%2];"
                             : "=r"(bf[nt][0]), "=r"(bf[nt][1]) : "r"(addr));
            }
#pragma unroll
            for (int mt = 0; mt < 4; ++mt)
#pragma unroll
                for (int nt = 0; nt < 4; ++nt) {
                    asm volatile(
                        "mma.sync.aligned.m16n8k16.row.col.f32.bf16.bf16.f32 "
                        "{%0,%1,%2,%3}, {%4,%5,%6,%7}, {%8,%9}, {%0,%1,%2,%3};"
                        : "+f"(acc[mt][nt][0]), "+f"(acc[mt][nt][1]),
                          "+f"(acc[mt][nt][2]), "+f"(acc[mt][nt][3])
                        : "r"(af[mt][0]), "r"(af[mt][1]), "r"(af[mt][2]), "r"(af[mt][3]),
                          "r"(bf[nt][0]), "r"(bf[nt][1]));
                }
        }

        if (t + 1 < nT) {
            const int nb = buf ^ 1;
            const int kb = (t + 1) * 32;
#pragma unroll
            for (int it = 0; it < 4; ++it) {
                float4 v = aReg[it];
                if (TA) {
                    int k0 = kb + ac;
                    v.x = fmaxf(v.x * scp[k0 + 0] + shp[k0 + 0], 0.f);
                    v.y = fmaxf(v.y * scp[k0 + 1] + shp[k0 + 1], 0.f);
                    v.z = fmaxf(v.z * scp[k0 + 2] + shp[k0 + 2], 0.f);
                    v.w = fmaxf(v.w * scp[k0 + 3] + shp[k0 + 3], 0.f);
                    if (lby + ar + it * 32 >= NNODES) v = make_float4(0.f, 0.f, 0.f, 0.f);
                }
                *(bf162*)&As[nb][ar + it * 32][ac]     = __floats2bfloat162_rn(v.x, v.y);
                *(bf162*)&As[nb][ar + it * 32][ac + 2] = __floats2bfloat162_rn(v.z, v.w);
            }
#pragma unroll
            for (int it = 0; it < 2; ++it)
                *(uint4*)&Bs[nb][bkr + it * 16][bc] = bReg[it];
            __syncthreads();
        }
    }

    // ---- store C (padded buffer: unconditional) ----
#pragma unroll
    for (int mt = 0; mt < 4; ++mt) {
        int r0 = by + warpM * 64 + mt * 16 + lq;
        int r1 = r0 + 8;
#pragma unroll
        for (int nt = 0; nt < 4; ++nt) {
            int c0 = bx + warpN * 32 + nt * 8 + lr * 2;
            *(float2*)(C + (size_t)r0 * Ncol + c0) = make_float2(acc[mt][nt][0], acc[mt][nt][1]);
            *(float2*)(C + (size_t)r1 * Ncol + c0) = make_float2(acc[mt][nt][2], acc[mt][nt][3]);
        }
    }

    // ---- fused BN stats (per half); pad rows contribute exact zeros ----
    for (int i = tid; i < 128; i += 256) { s_sum[i] = 0.f; s_sq[i] = 0.f; }
    __syncthreads();
#pragma unroll
    for (int nt = 0; nt < 4; ++nt) {
        float s0 = 0.f, q0 = 0.f, s1 = 0.f, q1 = 0.f;
#pragma unroll
        for (int mt = 0; mt < 4; ++mt) {
            float a0 = acc[mt][nt][0], a1 = acc[mt][nt][1];
            float a2 = acc[mt][nt][2], a3 = acc[mt][nt][3];
            s0 += a0 + a2; q0 += a0 * a0 + a2 * a2;
            s1 += a1 + a3; q1 += a1 * a1 + a3 * a3;
        }
#pragma unroll
        for (int o = 4; o < 32; o <<= 1) {
            s0 += __shfl_xor_sync(0xffffffffu, s0, o);
            q0 += __shfl_xor_sync(0xffffffffu, q0, o);
            s1 += __shfl_xor_sync(0xffffffffu, s1, o);
            q1 += __shfl_xor_sync(0xffffffffu, q1, o);
        }
        if (lq == 0) {
            int c0 = warpN * 32 + nt * 8 + lr * 2;
            atomicAdd(&s_sum[c0],     s0); atomicAdd(&s_sq[c0],     q0);
            atomicAdd(&s_sum[c0 + 1], s1); atomicAdd(&s_sq[c0 + 1], q1);
        }
    }
    __syncthreads();
    for (int i = tid; i < 128; i += 256) {
        atomicAdd(&st[bx + i],       s_sum[i]);
        atomicAdd(&st[512 + bx + i], s_sq[i]);
    }
}

// ---------------- decoder postbn + masked cosine loss, fused (warp/row) -------
__global__ void pbnloss_k(const float* __restrict__ V, float* __restrict__ REX,
                          const float* __restrict__ X,
                          const float* __restrict__ sc, const float* __restrict__ sh,
                          const unsigned char* __restrict__ mA, const unsigned char* __restrict__ mB,
                          float* __restrict__ acc) {
    int warp = threadIdx.x >> 5, lane = threadIdx.x & 31;
    int gr = blockIdx.x * 8 + warp;
    __shared__ float s_loss[2];
    if (threadIdx.x < 2) s_loss[threadIdx.x] = 0.f;
    __syncthreads();
    if (gr < 2 * NNODES) {
        int pass = gr >= NNODES;
        int r = gr - (pass ? NNODES : 0);
        size_t rowIdx = (size_t)(pass ? PADN : 0) + r;
        float4 v = ((const float4*)(V + rowIdx * D_IN))[lane];
        int k0 = pass * 512 + lane * 4;
        float4 a;
        a.x = fmaxf(v.x * sc[k0 + 0] + sh[k0 + 0], 0.f);
        a.y = fmaxf(v.y * sc[k0 + 1] + sh[k0 + 1], 0.f);
        a.z = fmaxf(v.z * sc[k0 + 2] + sh[k0 + 2], 0.f);
        a.w = fmaxf(v.w * sc[k0 + 3] + sh[k0 + 3], 0.f);
        ((float4*)(REX + rowIdx * D_IN))[lane] = a;
        float4 b = ((const float4*)(X + (size_t)r * D_IN))[lane];
        float dot = a.x * b.x + a.y * b.y + a.z * b.z + a.w * b.w;
        float na  = a.x * a.x + a.y * a.y + a.z * a.z + a.w * a.w;
        float nb  = b.x * b.x + b.y * b.y + b.z * b.z + b.w * b.w;
#pragma unroll
        for (int o = 16; o; o >>= 1) {
            dot += __shfl_down_sync(0xffffffffu, dot, o);
            na  += __shfl_down_sync(0xffffffffu, na , o);
            nb  += __shfl_down_sync(0xffffffffu, nb , o);
        }
        if (lane == 0 && (pass ? mB : mA)[r]) {
            float c = dot / (fmaxf(sqrtf(na), 1e-12f) * fmaxf(sqrtf(nb), 1e-12f));
            atomicAdd(&s_loss[pass], 1.f - c);
        }
    }
    __syncthreads();
    if (threadIdx.x < 2) {
        float t = s_loss[threadIdx.x];
        if (t != 0.f) atomicAdd(&acc[threadIdx.x], t);
    }
}

// ---------------- contrastive loss: cos(REX2, REX1) ----------------
__global__ void cl_k(const float* __restrict__ REX, float* __restrict__ acc) {
    int warp = threadIdx.x >> 5, lane = threadIdx.x & 31;
    int row = blockIdx.x * 8 + warp;
    float contrib = 0.f;
    if (row < NNODES) {
        float4 a = ((const float4*)(REX + (size_t)row * D_IN))[lane];
        float4 b = ((const float4*)(REX + ((size_t)PADN + row) * D_IN))[lane];
        float dot = a.x * b.x + a.y * b.y + a.z * b.z + a.w * b.w;
        float na  = a.x * a.x + a.y * a.y + a.z * a.z + a.w * a.w;
        float nb  = b.x * b.x + b.y * b.y + b.z * b.z + b.w * b.w;
#pragma unroll
        for (int o = 16; o; o >>= 1) {
            dot += __shfl_down_sync(0xffffffffu, dot, o);
            na  += __shfl_down_sync(0xffffffffu, na , o);
            nb  += __shfl_down_sync(0xffffffffu, nb , o);
        }
        if (lane == 0) {
            float c = dot / (fmaxf(sqrtf(na), 1e-12f) * fmaxf(sqrtf(nb), 1e-12f));
            contrib = 1.f - c;
        }
    }
    __shared__ float s[8];
    if (lane == 0) s[warp] = contrib;
    __syncthreads();
    if (threadIdx.x == 0) {
        float t = 0.f;
#pragma unroll
        for (int j = 0; j < 8; ++j) t += s[j];
        atomicAdd(acc, t);
    }
}

__global__ void final_k(float* __restrict__ out) {
    out[0] = g_acc[0] / g_acc[3] + g_acc[1] / g_acc[4] + 0.1f * (g_acc[2] / (float)NNODES);
}

extern "C" void kernel_launch(void* const* d_in, const int* in_sizes, int n_in,
                              void* d_out, int out_size) {
    const float* x = (const float*)d_in[0];
    const int* e1raw = (const int*)d_in[1];
    const int* e2raw = (const int*)d_in[2];
    const unsigned char* m1raw = (const unsigned char*)d_in[3];
    const unsigned char* m2raw = (const unsigned char*)d_in[4];
    const float* e0_w1 = (const float*)d_in[6];
    const float* e0_w2 = (const float*)d_in[7];
    const float* e0_bg = (const float*)d_in[8];
    const float* e0_bb = (const float*)d_in[9];
    const float* e0_ng = (const float*)d_in[10];
    const float* e0_nb = (const float*)d_in[11];
    const float* e1_w1 = (const float*)d_in[12];
    const float* e1_w2 = (const float*)d_in[13];
    const float* e1_bg = (const float*)d_in[14];
    const float* e1_bb = (const float*)d_in[15];
    const float* e1_ng = (const float*)d_in[16];
    const float* e1_nb = (const float*)d_in[17];
    const float* dw1   = (const float*)d_in[18];
    const float* dw2   = (const float*)d_in[19];
    const float* dbg   = (const float*)d_in[20];
    const float* dbb   = (const float*)d_in[21];
    const float* dng   = (const float*)d_in[22];
    const float* dnb   = (const float*)d_in[23];
    float* out = (float*)d_out;

    float *p_agg, *p_T, *p_V, *p_REX, *p_stats, *p_sc1, *p_sh1, *p_sc2, *p_sh2, *p_acc;
    bf16* p_wb;
    int *p_src1, *p_dst1, *p_src2, *p_dst2;
    unsigned char *p_mA, *p_mB;
    cudaGetSymbolAddress((void**)&p_agg,  g_agg);
    cudaGetSymbolAddress((void**)&p_T,    g_T);
    cudaGetSymbolAddress((void**)&p_V,    g_V);
    cudaGetSymbolAddress((void**)&p_REX,  g_REX);
    cudaGetSymbolAddress((void**)&p_stats,g_stats);
    cudaGetSymbolAddress((void**)&p_sc1,  g_sc1);
    cudaGetSymbolAddress((void**)&p_sh1,  g_sh1);
    cudaGetSymbolAddress((void**)&p_sc2,  g_sc2);
    cudaGetSymbolAddress((void**)&p_sh2,  g_sh2);
    cudaGetSymbolAddress((void**)&p_acc,  g_acc);
    cudaGetSymbolAddress((void**)&p_src1, g_src1);
    cudaGetSymbolAddress((void**)&p_dst1, g_dst1);
    cudaGetSymbolAddress((void**)&p_src2, g_src2);
    cudaGetSymbolAddress((void**)&p_dst2, g_dst2);
    cudaGetSymbolAddress((void**)&p_mA,   g_mA);
    cudaGetSymbolAddress((void**)&p_mB,   g_mB);
    cudaGetSymbolAddress((void**)&p_wb,   g_wb);

    bf16* wb_e0w1 = p_wb + 0;
    bf16* wb_e0w2 = p_wb + 65536;
    bf16* wb_e1w1 = p_wb + 196608;
    bf16* wb_e1w2 = p_wb + 327680;
    bf16* wb_dw1  = p_wb + 458752;
    bf16* wb_dw2  = p_wb + 589824;

    const unsigned EB = (NKEEP + 255) / 256;

    // ---- setup ----
    detect_k<<<1, 32>>>(e1raw, m1raw);
    prep_k<<<EB, 256>>>(e1raw, p_src1, p_dst1, m1raw, p_mA, p_acc + 3);
    prep_k<<<EB, 256>>>(e2raw, p_src2, p_dst2, m2raw, p_mB, p_acc + 4);
    convw_k<<<(65536  + 255) / 256, 256>>>(e0_w1, wb_e0w1, 65536);
    convw_k<<<(131072 + 255) / 256, 256>>>(e0_w2, wb_e0w2, 131072);
    convw_k<<<(131072 + 255) / 256, 256>>>(e1_w1, wb_e1w1, 131072);
    convw_k<<<(131072 + 255) / 256, 256>>>(e1_w2, wb_e1w2, 131072);
    convw_k<<<(131072 + 255) / 256, 256>>>(dw1,   wb_dw1,  131072);
    convw_k<<<(65536  + 255) / 256, 256>>>(dw2,   wb_dw2,  65536);

    const unsigned sgf = (2 * NKEEP + 7) / 8;     // scatterf: 8 edges/block
    const unsigned sgb = (2 * NKEEP + 3) / 4;     // scatterb: 4 edges/block
    const unsigned pbG = (unsigned)((2 * (size_t)NNODES * D_OUT + 255) / 256);

    // ---- encoder layer 0 ----
    maskagg_k<<<(unsigned)((2 * (size_t)NNODES * D_IN + 255) / 256), 256>>>(x, p_agg, p_mA, p_mB);
    scatterf_k<<<sgf, dim3(32, 8)>>>(x, p_agg, p_src1, p_dst1, p_src2, p_dst2, p_mA, p_mB);
    bgemm_k<false><<<dim3(4, 2 * YBLK), 256>>>(p_agg, wb_e0w1, p_T, D_IN, D_HID, nullptr, nullptr, p_stats);
    scaleshift_k<<<4, 256>>>(p_stats, e0_bg, e0_bb, p_sc1, p_sh1, D_HID);
    bgemm_k<true><<<dim3(2, 2 * YBLK), 256>>>(p_T, wb_e0w2, p_V, D_HID, D_OUT, p_sc1, p_sh1, p_stats);
    scaleshift_k<<<2, 256>>>(p_stats, e0_ng, e0_nb, p_sc2, p_sh2, D_OUT);
    postbn_k<false><<<pbG, 256>>>(p_V, p_agg, p_sc2, p_sh2, p_mA, p_mB);

    // ---- encoder layer 1 ----
    scatterb_k<false><<<sgb, dim3(64, 4)>>>(p_V, p_agg, p_src1, p_dst1, p_src2, p_dst2, p_sc2, p_sh2, p_mA, p_mB);
    bgemm_k<false><<<dim3(4, 2 * YBLK), 256>>>(p_agg, wb_e1w1, p_T, D_OUT, D_HID, nullptr, nullptr, p_stats);
    scaleshift_k<<<4, 256>>>(p_stats, e1_bg, e1_bb, p_sc1, p_sh1, D_HID);
    bgemm_k<true><<<dim3(2, 2 * YBLK), 256>>>(p_T, wb_e1w2, p_V, D_HID, D_OUT, p_sc1, p_sh1, p_stats);
    scaleshift_k<<<2, 256>>>(p_stats, e1_ng, e1_nb, p_sc2, p_sh2, D_OUT);
    postbn_k<true><<<pbG, 256>>>(p_V, p_agg, p_sc2, p_sh2, p_mA, p_mB);   // re_h mask

    // ---- decoder ----
    scatterb_k<true><<<sgb, dim3(64, 4)>>>(p_V, p_agg, p_src1, p_dst1, p_src2, p_dst2, p_sc2, p_sh2, p_mA, p_mB);
    bgemm_k<false><<<dim3(4, 2 * YBLK), 256>>>(p_agg, wb_dw1, p_T, D_OUT, D_HID, nullptr, nullptr, p_stats);
    scaleshift_k<<<4, 256>>>(p_stats, dbg, dbb, p_sc1, p_sh1, D_HID);
    bgemm_k<true><<<dim3(1, 2 * YBLK), 256>>>(p_T, wb_dw2, p_V, D_HID, D_IN, p_sc1, p_sh1, p_stats);
    scaleshift_k<<<1, 256>>>(p_stats, dng, dnb, p_sc2, p_sh2, D_IN);

    // fused decoder postbn + reconstruction losses
    pbnloss_k<<<(2 * NNODES + 7) / 8, 256>>>(p_V, p_REX, x, p_sc2, p_sh2, p_mA, p_mB, p_acc);
    cl_k<<<(NNODES + 7) / 8, 256>>>(p_REX, p_acc + 2);
    final_k<<<1, 1>>>(out);
    (void)in_sizes; (void)n_in; (void)out_size;
}